// round 9
// baseline (speedup 1.0000x reference)
#include <cuda_runtime.h>
#include <math.h>

#define BB 32
#define TT 1024
#define VV 5000
#define STEPS 64
#define JPAD 5008
#define NP 32            // attention T-parts
#define TCH 32           // t-chunk per part
#define TS 132           // tile stride (4 mod 32, 16B aligned)
#define GKS 8            // gates K-split (chunk 192)
#define LKS 4            // logits K-split (chunk 128)
#define LJT 157          // logits j-tiles of 32 (157*32 = 5024 >= 5000)
#define NB 592           // persistent blocks = 4 * 148 (guaranteed co-resident)

// ---------------- persistent device state ----------------
__device__ float g_actT[1536 * BB];          // [emb|ctx|h] transposed [k][b]
__device__ float g_hcT[1024 * BB];           // [h|ctx] transposed
__device__ float g_hRow[BB * 512];           // h row-major [b][i]
__device__ float g_cT[512 * BB];
__device__ float g_gatesP[GKS][2048 * BB];
__device__ float g_hidT[512 * BB];
__device__ float g_logitsP[LKS][BB * JPAD];
__device__ float g_eBuf[BB * TT];
__device__ float g_mP[NP * 128];
__device__ float g_sP[NP * 128];
__device__ float g_ctxP[NP][128 * 128];

// ---------------- grid barrier state ----------------
__device__ unsigned g_cnt;     // zero-init; returns to 0 after every barrier
__device__ unsigned g_gen;     // monotonic generation (relative targets)

__device__ __forceinline__ void grid_sync(unsigned target)
{
    __syncthreads();
    if (threadIdx.x == 0) {
        __threadfence();                       // release our phase's writes
        if (atomicAdd(&g_cnt, 1u) == NB - 1u) {
            g_cnt = 0u;
            __threadfence();
            atomicExch(&g_gen, target);        // release
        } else {
            volatile unsigned* vg = &g_gen;
            while (*vg != target) __nanosleep(64);
        }
        __threadfence();                       // acquire (invalidate L1)
    }
    __syncthreads();
}

// =================== the whole decode in ONE kernel ===================
__global__ void __launch_bounds__(256, 4)
decode_kernel(const float* __restrict__ lf,   const float* __restrict__ emb,
              const float* __restrict__ W_ih, const float* __restrict__ W_hh,
              const float* __restrict__ b_ih, const float* __restrict__ b_hh,
              const float* __restrict__ Wp,   const float* __restrict__ bp,
              const float* __restrict__ Wc,   const float* __restrict__ bc,
              float* __restrict__ out_pred,   float* __restrict__ out_attn)
{
    __shared__ __align__(16) float s_f[6176];   // 24.7 KB union across phases
    const int tid = threadIdx.x;

    unsigned gen = g_gen;    // stable: nobody modifies before first barrier
    unsigned k = 0;

    // ---- init: actT = [emb[0] | lf[:,0,:] | 0], c = 0 ----
    for (int idx = blockIdx.x * 256 + tid; idx < 1536 * BB; idx += NB * 256) {
        int b = idx & 31, kk = idx >> 5;
        float v;
        if (kk < 512)       v = emb[kk];
        else if (kk < 1024) v = lf[(size_t)b * TT * 512 + (kk - 512)];
        else              { v = 0.f; g_cT[(kk - 1024) * BB + b] = 0.f; }
        g_actT[idx] = v;
    }
    grid_sync(gen + (++k));

    for (int s = 0; s < STEPS; s++) {
        // ============ phase 1: gates GEMM (1024 tiles, 2 per block) ============
        {
            int half = tid >> 7, htid = tid & 127;
            float* ws = s_f + half * 3088;      // 16*193
            for (int vp = blockIdx.x; vp < 512; vp += NB) {
                int vt = vp * 2 + half;
                int j0 = (vt & 127) * 16, base = (vt >> 7) * 192;
                for (int idx = htid; idx < 16 * 192; idx += 128) {
                    int r = idx / 192, kk = idx - r * 192;
                    int kg = base + kk, j = j0 + r;
                    ws[r * 193 + kk] = (kg < 1024) ? W_ih[(size_t)j * 1024 + kg]
                                                   : W_hh[(size_t)j * 512 + (kg - 1024)];
                }
                __syncthreads();
                int bg = htid & 7, jj = htid >> 3;
                const float* wr = ws + jj * 193;
                const float4* xv = (const float4*)g_actT;
                float ax = 0.f, ay = 0.f, az = 0.f, aw = 0.f;
                #pragma unroll 8
                for (int kk = 0; kk < 192; kk++) {
                    float w = wr[kk];
                    float4 x = xv[(base + kk) * 8 + bg];
                    ax = fmaf(w, x.x, ax); ay = fmaf(w, x.y, ay);
                    az = fmaf(w, x.z, az); aw = fmaf(w, x.w, aw);
                }
                ((float4*)g_gatesP[vt >> 7])[(j0 + jj) * 8 + bg] = make_float4(ax, ay, az, aw);
                __syncthreads();
            }
        }
        grid_sync(gen + (++k));

        // ============ phase 2: LSTM pointwise (16 block-slots) ============
        for (int idx = blockIdx.x * 256 + tid; idx < 512 * 8; idx += NB * 256) {
            int b4 = idx & 7, i = idx >> 3;
            float4 g4[4];
            #pragma unroll
            for (int g = 0; g < 4; g++) {
                int j = g * 512 + i;
                float bias = b_ih[j] + b_hh[j];
                float4 v = make_float4(bias, bias, bias, bias);
                #pragma unroll
                for (int p = 0; p < GKS; p++) {
                    float4 x = ((const float4*)g_gatesP[p])[j * 8 + b4];
                    v.x += x.x; v.y += x.y; v.z += x.z; v.w += x.w;
                }
                g4[g] = v;
            }
            float4 c = ((const float4*)g_cT)[i * 8 + b4];
            float4 hv;
            {
                float cc, h;
                #define DO_LANE(L) { \
                    float si = 1.f / (1.f + __expf(-g4[0].L)); \
                    float sf = 1.f / (1.f + __expf(-g4[1].L)); \
                    float tg = tanhf(g4[2].L); \
                    float so = 1.f / (1.f + __expf(-g4[3].L)); \
                    cc = sf * c.L + si * tg; c.L = cc; \
                    h = so * tanhf(cc); hv.L = h; }
                DO_LANE(x) DO_LANE(y) DO_LANE(z) DO_LANE(w)
                #undef DO_LANE
            }
            ((float4*)g_cT)[i * 8 + b4] = c;
            ((float4*)(g_actT + 1024 * BB))[i * 8 + b4] = hv;
            ((float4*)g_hcT)[i * 8 + b4] = hv;
            int b0 = b4 * 4;
            g_hRow[(b0 + 0) * 512 + i] = hv.x;
            g_hRow[(b0 + 1) * 512 + i] = hv.y;
            g_hRow[(b0 + 2) * 512 + i] = hv.z;
            g_hRow[(b0 + 3) * 512 + i] = hv.w;
        }
        grid_sync(gen + (++k));

        // ============ phase 3: attention partials (4096 tiles) ============
        {
            float* tile = s_f;                     // 32*132
            float* ds_s = s_f + 4224;              // 128
            float* ep   = s_f + 4352;              // 8*32
            float* csh  = s_f + 4608;              // 8*132
            float* e_s  = s_f + 5664;              // 32
            for (int vb = blockIdx.x; vb < 128 * NP; vb += NB) {
                int b = vb & 31, hh = (vb >> 5) & 3, part = vb >> 7;
                int t0 = part * TCH;
                if (tid < 128) ds_s[tid] = g_hRow[b * 512 + hh * 128 + tid];
                const float4* src = (const float4*)(lf + ((size_t)b * TT + t0) * 512 + hh * 128);
                #pragma unroll
                for (int it = 0; it < 4; it++) {
                    int idx = tid + it * 256;
                    int t = idx >> 5, c = idx & 31;
                    ((float4*)&tile[t * TS])[c] = src[(size_t)t * 128 + c];
                }
                __syncthreads();

                {   // energy partials: (dg 0..7, t 0..31)
                    int t = tid & 31, dg = tid >> 5;
                    const float4* tr = (const float4*)&tile[t * TS + dg * 16];
                    const float4* dsp = (const float4*)&ds_s[dg * 16];
                    float a = 0.f;
                    #pragma unroll
                    for (int i = 0; i < 4; i++) {
                        float4 v = tr[i], d = dsp[i];
                        a = fmaf(d.x, v.x, a); a = fmaf(d.y, v.y, a);
                        a = fmaf(d.z, v.z, a); a = fmaf(d.w, v.w, a);
                    }
                    ep[dg * TCH + t] = a;
                }
                __syncthreads();

                int bh = b * 4 + hh;
                if (tid < TCH) {
                    float e = ep[tid];
                    #pragma unroll
                    for (int q = 1; q < 8; q++) e += ep[q * TCH + tid];
                    if (hh == 3) g_eBuf[b * TT + t0 + tid] = e;
                    float m = e;
                    #pragma unroll
                    for (int off = 16; off; off >>= 1) m = fmaxf(m, __shfl_xor_sync(~0u, m, off));
                    float p = __expf(e - m);
                    e_s[tid] = p;
                    float ss = p;
                    #pragma unroll
                    for (int off = 16; off; off >>= 1) ss += __shfl_xor_sync(~0u, ss, off);
                    if (tid == 0) { g_mP[part * 128 + bh] = m; g_sP[part * 128 + bh] = ss; }
                }
                __syncthreads();

                {   // context partial: (dq 0..31, tg 0..7)
                    int dq = tid & 31, tg = tid >> 5;
                    float4 acc = make_float4(0.f, 0.f, 0.f, 0.f);
                    #pragma unroll
                    for (int i = 0; i < 4; i++) {
                        int t = tg * 4 + i;
                        float p = e_s[t];
                        float4 v = *(const float4*)&tile[t * TS + dq * 4];
                        acc.x = fmaf(p, v.x, acc.x); acc.y = fmaf(p, v.y, acc.y);
                        acc.z = fmaf(p, v.z, acc.z); acc.w = fmaf(p, v.w, acc.w);
                    }
                    ((float4*)&csh[tg * TS])[dq] = acc;
                }
                __syncthreads();
                if (tid < 128) {
                    float ss = 0.f;
                    #pragma unroll
                    for (int tg = 0; tg < 8; tg++) ss += csh[tg * TS + tid];
                    g_ctxP[part][bh * 128 + tid] = ss;
                }
                __syncthreads();
            }
        }
        grid_sync(gen + (++k));

        // ============ phase 4: attention combine (128 tiles) ============
        {
            float* w_s = s_f;          // 32
            float* MsSs = s_f + 32;    // 2
            float* attn_row = out_attn + (size_t)s * BB * TT;
            for (int vb = blockIdx.x; vb < 128; vb += NB) {
                int b = vb & 31, hh = vb >> 5;
                int bh = b * 4 + hh;
                if (tid < 32) {
                    float m = g_mP[tid * 128 + bh];
                    float sp = g_sP[tid * 128 + bh];
                    float M = m;
                    #pragma unroll
                    for (int off = 16; off; off >>= 1) M = fmaxf(M, __shfl_xor_sync(~0u, M, off));
                    float w = __expf(m - M);
                    w_s[tid] = w;
                    float ss = sp * w;
                    #pragma unroll
                    for (int off = 16; off; off >>= 1) ss += __shfl_xor_sync(~0u, ss, off);
                    if (tid == 0) { MsSs[0] = M; MsSs[1] = ss; }
                }
                __syncthreads();
                float inv = 1.f / MsSs[1];
                float M = MsSs[0];
                if (tid < 128) {
                    float ctx = 0.f;
                    #pragma unroll
                    for (int p = 0; p < NP; p++) ctx = fmaf(g_ctxP[p][bh * 128 + tid], w_s[p], ctx);
                    ctx *= inv;
                    int d = hh * 128 + tid;
                    g_actT[(512 + d) * BB + b] = ctx;
                    g_hcT[(512 + d) * BB + b] = ctx;
                    if (hh == 3) {
                        #pragma unroll
                        for (int i = 0; i < 8; i++) {
                            int t = tid + i * 128;
                            __stcs(&attn_row[(size_t)b * TT + t], __expf(g_eBuf[b * TT + t] - M) * inv);
                        }
                    }
                }
                __syncthreads();
            }
        }
        grid_sync(gen + (++k));

        // ============ phase 5: predict_hid (128 tiles) ============
        {
            float* ph = s_f;   // 8*32
            for (int vb = blockIdx.x; vb < 128; vb += NB) {
                int wid = tid >> 5, lane = tid & 31;
                int jj = wid >> 1, half = wid & 1;
                int j = vb * 4 + jj;
                const float4* wv = (const float4*)(Wp + (size_t)j * 1024 + half * 512);
                const float* x = g_hcT + half * 512 * BB;
                float acc = 0.f;
                #pragma unroll 8
                for (int k4 = 0; k4 < 128; k4++) {
                    float4 wq = wv[k4];
                    int kk = k4 * 4;
                    acc = fmaf(wq.x, x[(kk + 0) * BB + lane], acc);
                    acc = fmaf(wq.y, x[(kk + 1) * BB + lane], acc);
                    acc = fmaf(wq.z, x[(kk + 2) * BB + lane], acc);
                    acc = fmaf(wq.w, x[(kk + 3) * BB + lane], acc);
                }
                ph[wid * 32 + lane] = acc;
                __syncthreads();
                if (wid < 4) {
                    int j2 = vb * 4 + wid;
                    float v = ph[wid * 64 + lane] + ph[wid * 64 + 32 + lane] + bp[j2];
                    g_hidT[j2 * BB + lane] = fmaxf(v, 0.f);
                }
                __syncthreads();
            }
        }
        grid_sync(gen + (++k));

        // ============ phase 6: logits GEMM (157 jt x 4 parts = 628 tiles) ============
        {
            float* ws = s_f;   // 32*129
            for (int vb = blockIdx.x; vb < LJT * LKS; vb += NB) {
                int jt = vb % LJT, part = vb / LJT;
                int j0 = jt * 32, base = part * 128;
                for (int idx = tid; idx < 32 * 128; idx += 256) {
                    int r = idx >> 7, kk = idx & 127;
                    int j = j0 + r;
                    ws[r * 129 + kk] = (j < VV) ? Wc[(size_t)j * 512 + base + kk] : 0.f;
                }
                __syncthreads();
                int bg = tid & 7, jj = tid >> 3;    // 8 x 32
                int j = j0 + jj;
                const float* wr = ws + jj * 129;
                const float4* xv = (const float4*)g_hidT;
                float ax = 0.f, ay = 0.f, az = 0.f, aw = 0.f;
                #pragma unroll 8
                for (int kk = 0; kk < 128; kk++) {
                    float w = wr[kk];
                    float4 x = xv[(base + kk) * 8 + bg];
                    ax = fmaf(w, x.x, ax); ay = fmaf(w, x.y, ay);
                    az = fmaf(w, x.z, az); aw = fmaf(w, x.w, aw);
                }
                if (j < VV) {
                    float* dst = g_logitsP[part];
                    int b0 = bg * 4;
                    dst[(size_t)(b0 + 0) * JPAD + j] = ax;
                    dst[(size_t)(b0 + 1) * JPAD + j] = ay;
                    dst[(size_t)(b0 + 2) * JPAD + j] = az;
                    dst[(size_t)(b0 + 3) * JPAD + j] = aw;
                }
                __syncthreads();
            }
        }
        grid_sync(gen + (++k));

        // ============ phase 7: log_softmax + argmax + feedback (32 tiles) ============
        {
            float* v_s = s_f;                 // 5000
            float* sv  = s_f + 5000;          // 256
            int*   si  = (int*)(s_f + 5256);  // 256
            int*   tok_s = (int*)(s_f + 5512);
            float* pred_row = out_pred + (size_t)s * BB * VV;
            for (int vb = blockIdx.x; vb < 32; vb += NB) {
                int b = vb;
                const float4* p0 = (const float4*)(g_logitsP[0] + (size_t)b * JPAD);
                const float4* p1 = (const float4*)(g_logitsP[1] + (size_t)b * JPAD);
                const float4* p2 = (const float4*)(g_logitsP[2] + (size_t)b * JPAD);
                const float4* p3 = (const float4*)(g_logitsP[3] + (size_t)b * JPAD);
                const float4* bcv = (const float4*)bc;
                for (int j4 = tid; j4 < VV / 4; j4 += 256) {
                    float4 a = p0[j4], c = p1[j4], d = p2[j4], e = p3[j4], f = bcv[j4];
                    float4 r;
                    r.x = a.x + c.x + d.x + e.x + f.x;
                    r.y = a.y + c.y + d.y + e.y + f.y;
                    r.z = a.z + c.z + d.z + e.z + f.z;
                    r.w = a.w + c.w + d.w + e.w + f.w;
                    ((float4*)v_s)[j4] = r;
                }
                __syncthreads();

                float m = -1e30f; int mi = VV;
                for (int j = tid; j < VV; j += 256) {
                    float v = v_s[j];
                    if (v > m) { m = v; mi = j; }
                }
                sv[tid] = m; si[tid] = mi; __syncthreads();
                for (int st = 128; st; st >>= 1) {
                    if (tid < st) {
                        float v2 = sv[tid + st]; int i2 = si[tid + st];
                        if (v2 > sv[tid] || (v2 == sv[tid] && i2 < si[tid])) { sv[tid] = v2; si[tid] = i2; }
                    }
                    __syncthreads();
                }
                float mm = sv[0];
                if (tid == 0) *tok_s = si[0];
                __syncthreads();

                float ssum = 0.f;
                for (int j = tid; j < VV; j += 256) ssum += __expf(v_s[j] - mm);
                sv[tid] = ssum; __syncthreads();
                for (int st = 128; st; st >>= 1) {
                    if (tid < st) sv[tid] += sv[tid + st];
                    __syncthreads();
                }
                float lse = mm + logf(sv[0]);

                float4* row = (float4*)(pred_row + (size_t)b * VV);
                for (int j4 = tid; j4 < VV / 4; j4 += 256) {
                    float4 v = ((float4*)v_s)[j4];
                    v.x -= lse; v.y -= lse; v.z -= lse; v.w -= lse;
                    __stcs(&row[j4], v);
                }

                int tok = *tok_s;
                for (int kk = tid; kk < 512; kk += 256)
                    g_actT[kk * BB + b] = emb[(size_t)tok * 512 + kk];
                __syncthreads();
            }
        }
        grid_sync(gen + (++k));
    }
}

// ---------------- launcher ----------------
extern "C" void kernel_launch(void* const* d_in, const int* in_sizes, int n_in,
                              void* d_out, int out_size)
{
    const float* lf   = (const float*)d_in[0];
    const float* emb  = (const float*)d_in[1];
    const float* W_ih = (const float*)d_in[2];
    const float* W_hh = (const float*)d_in[3];
    const float* b_ih = (const float*)d_in[4];
    const float* b_hh = (const float*)d_in[5];
    const float* Wp   = (const float*)d_in[6];
    const float* bp   = (const float*)d_in[7];
    const float* Wc   = (const float*)d_in[8];
    const float* bc   = (const float*)d_in[9];

    float* out      = (float*)d_out;
    float* out_pred = out;
    float* out_attn = out + (size_t)STEPS * BB * VV;

    decode_kernel<<<NB, 256>>>(lf, emb, W_ih, W_hh, b_ih, b_hh,
                               Wp, bp, Wc, bc, out_pred, out_attn);
}